// round 2
// baseline (speedup 1.0000x reference)
#include <cuda_runtime.h>
#include <cstddef>

// Problem constants (fixed shapes from reference)
#define BB 16384
#define GG 128
#define SS 64
#define HH 10
#define PHH 100

// 8MB scratch for gene_layer, stored TRANSPOSED: glT[g][b]
__device__ float g_glT[GG * BB];

// ---------------------------------------------------------------------------
// packed fp32x2 FMA (Blackwell sm_100+; only reachable via inline PTX)
// ---------------------------------------------------------------------------
__device__ __forceinline__ unsigned long long f2fma(unsigned long long a,
                                                    unsigned long long b,
                                                    unsigned long long c) {
    unsigned long long d;
    asm("fma.rn.f32x2 %0, %1, %2, %3;" : "=l"(d) : "l"(a), "l"(b), "l"(c));
    return d;
}
__device__ __forceinline__ float f2lo(unsigned long long a) {
    return __uint_as_float((unsigned)a);
}
__device__ __forceinline__ float f2hi(unsigned long long a) {
    return __uint_as_float((unsigned)(a >> 32));
}
__device__ __forceinline__ unsigned long long f2dup(float v) {
    unsigned long long d;
    asm("mov.b64 %0, {%1, %1};" : "=l"(d) : "f"(v));
    return d;
}

extern __shared__ unsigned char dynsmem[];

// ---------------------------------------------------------------------------
// Kernel A: per-gene MLP  gene_layer[b,g] = W2 . relu(x[b,g,:] @ W1[g] + b1) + b2
// Grid: (B/256, G). 64 threads, 4 rows/thread (amortizes W-broadcast LDS 4x).
// ---------------------------------------------------------------------------
#define A_ROWS 256
#define A_THREADS 64
#define XSTR (A_ROWS + 1)   // row-dim stride in ulonglong2 units (pad vs banks)

// dyn smem: xq[16][XSTR] ulonglong2 | wq[10][16] ulonglong2 | sb1[16] sW2[16] sb2[4]
#define A_SMEM_BYTES (16 * XSTR * 16 + 10 * 16 * 16 + (16 + 16 + 4) * 4)

__global__ void __launch_bounds__(A_THREADS)
kernelA(const float* __restrict__ x, const float* __restrict__ W1,
        const float* __restrict__ b1, const float* __restrict__ W2,
        const float* __restrict__ b2) {
    ulonglong2* xq = (ulonglong2*)dynsmem;                 // [16][XSTR]
    ulonglong2* wq = xq + 16 * XSTR;                       // [10][16]
    float* ftail = (float*)(wq + 10 * 16);
    float* sb1 = ftail;        // [16]
    float* sW2 = ftail + 16;   // [16]
    float* sb2 = ftail + 32;   // [1]

    const int tid = threadIdx.x;
    const int g = blockIdx.y;
    const int b0 = blockIdx.x * A_ROWS;

    // --- stage W1[g] packed: wq[h][q] = 4 floats {W1[4q..4q+3][h]} ---
    {
        const float* W1g = W1 + g * (SS * HH);
        float* wqf = (float*)wq;
        for (int i = tid; i < SS * HH; i += A_THREADS) {
            int s = i / HH, h = i - s * HH;
            wqf[(h * 16 + (s >> 2)) * 4 + (s & 3)] = W1g[i];
        }
        if (tid < HH) {
            sb1[tid] = b1[g * HH + tid];
            sW2[tid] = W2[g * HH + tid];
        }
        if (tid == 0) sb2[0] = b2[g];
    }

    // --- stage x tile transposed: xq[q][r] = x[b0+r, g, 4q..4q+3] ---
    // warp instruction covers two contiguous 256B rows -> fully coalesced
#pragma unroll 8
    for (int i = tid; i < A_ROWS * 16; i += A_THREADS) {
        int q = i & 15, r = i >> 4;
        const ulonglong2* src =
            (const ulonglong2*)(x + (((size_t)(b0 + r)) * GG + g) * SS);
        xq[q * XSTR + r] = src[q];
    }
    __syncthreads();

    // --- compute: 4 rows per thread, 10 h, f32x2 over s-pairs ---
    unsigned long long a0[HH], a1[HH], a2[HH], a3[HH];
#pragma unroll
    for (int h = 0; h < HH; h++) { a0[h] = 0ull; a1[h] = 0ull; a2[h] = 0ull; a3[h] = 0ull; }

    const int r0 = tid;
#pragma unroll 4
    for (int q = 0; q < 16; q++) {
        ulonglong2 xa = xq[q * XSTR + r0];          // conflict-free: lanes = rows
        ulonglong2 xb = xq[q * XSTR + r0 + 64];
        ulonglong2 xc = xq[q * XSTR + r0 + 128];
        ulonglong2 xd = xq[q * XSTR + r0 + 192];
#pragma unroll
        for (int h = 0; h < HH; h++) {
            ulonglong2 w = wq[h * 16 + q];          // broadcast, amortized 4 rows
            a0[h] = f2fma(xa.x, w.x, a0[h]);
            a1[h] = f2fma(xb.x, w.x, a1[h]);
            a2[h] = f2fma(xc.x, w.x, a2[h]);
            a3[h] = f2fma(xd.x, w.x, a3[h]);
            a0[h] = f2fma(xa.y, w.y, a0[h]);
            a1[h] = f2fma(xb.y, w.y, a1[h]);
            a2[h] = f2fma(xc.y, w.y, a2[h]);
            a3[h] = f2fma(xd.y, w.y, a3[h]);
        }
    }

    // --- epilogue: relu + H->1 projection, coalesced store to glT ---
    float o0 = sb2[0], o1 = sb2[0], o2 = sb2[0], o3 = sb2[0];
#pragma unroll
    for (int h = 0; h < HH; h++) {
        float v0 = f2lo(a0[h]) + f2hi(a0[h]) + sb1[h];
        float v1 = f2lo(a1[h]) + f2hi(a1[h]) + sb1[h];
        float v2 = f2lo(a2[h]) + f2hi(a2[h]) + sb1[h];
        float v3 = f2lo(a3[h]) + f2hi(a3[h]) + sb1[h];
        v0 = fmaxf(v0, 0.f); v1 = fmaxf(v1, 0.f);
        v2 = fmaxf(v2, 0.f); v3 = fmaxf(v3, 0.f);
        o0 = fmaf(v0, sW2[h], o0);
        o1 = fmaf(v1, sW2[h], o1);
        o2 = fmaf(v2, sW2[h], o2);
        o3 = fmaf(v3, sW2[h], o3);
    }
    float* glrow = g_glT + (size_t)g * BB + b0;
    glrow[r0]       = o0;
    glrow[r0 + 64]  = o1;
    glrow[r0 + 128] = o2;
    glrow[r0 + 192] = o3;
}

// ---------------------------------------------------------------------------
// Kernel B: out[b] = relu(gl[b,:] @ Wp1 + bp1) @ Wp2 + bp2
// Grid: B/64 = 256 blocks, 512 threads = 64 rows x 8 j-subsets (16 j each,
// PH padded 100 -> 128 with zeros). f32x2 packed over j-pairs.
// ---------------------------------------------------------------------------
#define B_THREADS 512
#define B_ROWSB 64
#define PHP 128   // padded PH
#define B_SMEM_FLOATS (GG * B_ROWSB + GG * PHP + PHP + PHP + 8 * B_ROWSB)
#define B_SMEM_BYTES (B_SMEM_FLOATS * 4)

__global__ void __launch_bounds__(B_THREADS)
kernelB(const float* __restrict__ Wp1, const float* __restrict__ bp1,
        const float* __restrict__ Wp2, const float* __restrict__ bp2,
        float* __restrict__ out) {
    float* gls  = (float*)dynsmem;            // [G][64] rows of this tile (g-major)
    float* sWp1 = gls + GG * B_ROWSB;         // [G][128] zero-padded
    float* sbp1 = sWp1 + GG * PHP;            // [128] zero-padded
    float* sWp2 = sbp1 + PHP;                 // [128] zero-padded
    float* op   = sWp2 + PHP;                 // [8][64] partial outputs

    const int tid = threadIdx.x;
    const int b0 = blockIdx.x * B_ROWSB;

    // stage gene_layer tile from transposed scratch (coalesced: rows contiguous)
#pragma unroll 4
    for (int i = tid; i < GG * B_ROWSB; i += B_THREADS) {
        int r = i & (B_ROWSB - 1), g = i >> 6;
        gls[g * B_ROWSB + r] = g_glT[(size_t)g * BB + b0 + r];
    }
    // stage Wp1 zero-padded to 128 columns
#pragma unroll 4
    for (int i = tid; i < GG * PHP; i += B_THREADS) {
        int g = i >> 7, j = i & (PHP - 1);
        sWp1[i] = (j < PHH) ? Wp1[g * PHH + j] : 0.f;
    }
    if (tid < PHP) {
        sbp1[tid] = (tid < PHH) ? bp1[tid] : 0.f;
        sWp2[tid] = (tid < PHH) ? Wp2[tid] : 0.f;
    }
    __syncthreads();

    const int row  = tid & (B_ROWSB - 1);   // lane -> row (conflict-free LDS)
    const int jsub = tid >> 6;              // warp-uniform j subset
    const int jb   = jsub * 16;

    unsigned long long acc[8];
#pragma unroll
    for (int c = 0; c < 8; c++) acc[c] = 0ull;

#pragma unroll 8
    for (int g = 0; g < GG; g++) {
        float xs = gls[g * B_ROWSB + row];
        unsigned long long xx = f2dup(xs);
        const ulonglong2* wp = (const ulonglong2*)(sWp1 + g * PHP + jb);
        ulonglong2 w0 = wp[0];    // broadcast: j pairs 0..3
        ulonglong2 w1 = wp[1];    // j pairs 4..7
        acc[0] = f2fma(xx, w0.x, acc[0]);
        acc[1] = f2fma(xx, w0.y, acc[1]);
        acc[2] = f2fma(xx, w1.x, acc[2]);
        acc[3] = f2fma(xx, w1.y, acc[3]);
        ulonglong2 w2 = wp[2];
        ulonglong2 w3 = wp[3];
        acc[4] = f2fma(xx, w2.x, acc[4]);
        acc[5] = f2fma(xx, w2.y, acc[5]);
        acc[6] = f2fma(xx, w3.x, acc[6]);
        acc[7] = f2fma(xx, w3.y, acc[7]);
    }

    float o = 0.f;
#pragma unroll
    for (int c = 0; c < 8; c++) {
        int j0 = jb + 2 * c, j1 = j0 + 1;
        float p0 = fmaxf(f2lo(acc[c]) + sbp1[j0], 0.f);
        float p1 = fmaxf(f2hi(acc[c]) + sbp1[j1], 0.f);
        o = fmaf(p0, sWp2[j0], o);
        o = fmaf(p1, sWp2[j1], o);
    }
    op[jsub * B_ROWSB + row] = o;
    __syncthreads();

    if (tid < B_ROWSB) {
        float v = bp2[0];
#pragma unroll
        for (int c = 0; c < 8; c++) v += op[c * B_ROWSB + tid];
        out[b0 + tid] = v;
    }
}

// ---------------------------------------------------------------------------
extern "C" void kernel_launch(void* const* d_in, const int* in_sizes, int n_in,
                              void* d_out, int out_size) {
    const float* x   = (const float*)d_in[0];
    const float* W1  = (const float*)d_in[1];
    const float* b1  = (const float*)d_in[2];
    const float* W2  = (const float*)d_in[3];
    const float* b2  = (const float*)d_in[4];
    const float* Wp1 = (const float*)d_in[5];
    const float* bp1 = (const float*)d_in[6];
    const float* Wp2 = (const float*)d_in[7];
    const float* bp2 = (const float*)d_in[8];
    float* out = (float*)d_out;

    // idempotent, called every launch (no static guards allowed)
    cudaFuncSetAttribute(kernelA, cudaFuncAttributeMaxDynamicSharedMemorySize,
                         A_SMEM_BYTES);
    cudaFuncSetAttribute(kernelB, cudaFuncAttributeMaxDynamicSharedMemorySize,
                         B_SMEM_BYTES);

    dim3 gridA(BB / A_ROWS, GG);
    kernelA<<<gridA, A_THREADS, A_SMEM_BYTES>>>(x, W1, b1, W2, b2);

    dim3 gridB(BB / B_ROWSB);
    kernelB<<<gridB, B_THREADS, B_SMEM_BYTES>>>(Wp1, bp1, Wp2, bp2, out);
}

// round 3
// speedup vs baseline: 1.2942x; 1.2942x over previous
#include <cuda_runtime.h>
#include <cstddef>

// Problem constants (fixed shapes from reference)
#define BB 16384
#define GG 128
#define SS 64
#define HH 10
#define PHH 100

// 8MB scratch for gene_layer, stored TRANSPOSED: glT[g][b]
__device__ float g_glT[GG * BB];

// ---------------------------------------------------------------------------
// packed fp32x2 FMA (Blackwell sm_100+; only reachable via inline PTX)
// ---------------------------------------------------------------------------
__device__ __forceinline__ unsigned long long f2fma(unsigned long long a,
                                                    unsigned long long b,
                                                    unsigned long long c) {
    unsigned long long d;
    asm("fma.rn.f32x2 %0, %1, %2, %3;" : "=l"(d) : "l"(a), "l"(b), "l"(c));
    return d;
}
__device__ __forceinline__ float f2lo(unsigned long long a) {
    return __uint_as_float((unsigned)a);
}
__device__ __forceinline__ float f2hi(unsigned long long a) {
    return __uint_as_float((unsigned)(a >> 32));
}
__device__ __forceinline__ unsigned long long f2dup(float v) {
    unsigned long long d;
    asm("mov.b64 %0, {%1, %1};" : "=l"(d) : "f"(v));
    return d;
}

extern __shared__ unsigned char dynsmem[];

// ---------------------------------------------------------------------------
// Kernel A: per-gene MLP  gene_layer[b,g] = W2 . relu(x[b,g,:] @ W1[g] + b1) + b2
// One block = (gene g, 128-row tile). 128 threads, thread = one row.
// x staged coalesced into padded row-major smem, pulled into 64 regs/thread,
// W broadcast from smem with h as the OUTER loop (16 LDS.128 per h per warp).
// ---------------------------------------------------------------------------
#define AR 128      // rows per block
#define ATH 128     // threads
#define XPAD 68     // floats per row in smem (64 + 4 pad: conflict-free phases)

__global__ void __launch_bounds__(ATH)
kernelA(const float* __restrict__ x, const float* __restrict__ W1,
        const float* __restrict__ b1, const float* __restrict__ W2,
        const float* __restrict__ b2) {
    __shared__ float xs[AR * XPAD];        // 34816 B
    __shared__ float wt[HH * SS];          // [h][s], 2560 B
    __shared__ float sb1[HH], sW2[HH], sb2v[1];

    const int tid = threadIdx.x;
    const int g = blockIdx.x;
    const int b0 = blockIdx.y * AR;

    // --- stage W1[g] transposed: wt[h][s] = W1[g][s][h] (tiny) ---
    {
        const float* W1g = W1 + (size_t)g * (SS * HH);
        for (int i = tid; i < SS * HH; i += ATH) {
            int s = i / HH, h = i - s * HH;
            wt[h * SS + s] = W1g[i];
        }
        if (tid < HH) {
            sb1[tid] = b1[g * HH + tid];
            sW2[tid] = W2[g * HH + tid];
        }
        if (tid == 0) sb2v[0] = b2[g];
    }

    // --- stage x tile coalesced: xs[r][0..63] = x[b0+r, g, :] ---
    // 16 lanes cover one 256B row contiguously -> 512B fully-used wavefronts
#pragma unroll 8
    for (int i = tid; i < AR * 16; i += ATH) {
        int r = i >> 4, q = i & 15;
        float4 v = *(const float4*)(x + (((size_t)(b0 + r)) * GG + g) * SS + 4 * q);
        *(float4*)(xs + r * XPAD + 4 * q) = v;
    }
    __syncthreads();

    // --- pull own row into registers (conflict-free: pad 68 => 8-lane phases hit
    //     distinct banks) ---
    ulonglong2 xr[16];
#pragma unroll
    for (int q = 0; q < 16; q++)
        xr[q] = *(const ulonglong2*)(xs + tid * XPAD + 4 * q);

    // --- h-outer loop: 16 broadcast LDS.128 of W per h, 32 FFMA2 per h ---
    float o = sb2v[0];
#pragma unroll 1
    for (int h = 0; h < HH; h++) {
        unsigned long long acc0 = 0ull, acc1 = 0ull;
        const float* wrow = wt + h * SS;
#pragma unroll
        for (int q = 0; q < 16; q++) {
            ulonglong2 w = *(const ulonglong2*)(wrow + 4 * q);  // broadcast
            acc0 = f2fma(xr[q].x, w.x, acc0);
            acc1 = f2fma(xr[q].y, w.y, acc1);
        }
        float v = (f2lo(acc0) + f2hi(acc0)) + (f2lo(acc1) + f2hi(acc1)) + sb1[h];
        o = fmaf(fmaxf(v, 0.f), sW2[h], o);
    }
    g_glT[(size_t)g * BB + b0 + tid] = o;
}

// ---------------------------------------------------------------------------
// Kernel B: out[b] = relu(gl[b,:] @ Wp1 + bp1) @ Wp2 + bp2
// Grid: B/64 = 256 blocks, 512 threads = 64 rows x 8 j-subsets (16 j each,
// PH padded 100 -> 128 with zeros). f32x2 packed over j-pairs.
// ---------------------------------------------------------------------------
#define B_THREADS 512
#define B_ROWSB 64
#define PHP 128   // padded PH
#define B_SMEM_FLOATS (GG * B_ROWSB + GG * PHP + PHP + PHP + 8 * B_ROWSB)
#define B_SMEM_BYTES (B_SMEM_FLOATS * 4)

__global__ void __launch_bounds__(B_THREADS)
kernelB(const float* __restrict__ Wp1, const float* __restrict__ bp1,
        const float* __restrict__ Wp2, const float* __restrict__ bp2,
        float* __restrict__ out) {
    float* gls  = (float*)dynsmem;            // [G][64] rows of this tile (g-major)
    float* sWp1 = gls + GG * B_ROWSB;         // [G][128] zero-padded
    float* sbp1 = sWp1 + GG * PHP;            // [128] zero-padded
    float* sWp2 = sbp1 + PHP;                 // [128] zero-padded
    float* op   = sWp2 + PHP;                 // [8][64] partial outputs

    const int tid = threadIdx.x;
    const int b0 = blockIdx.x * B_ROWSB;

    // stage gene_layer tile from transposed scratch (coalesced: rows contiguous)
#pragma unroll 4
    for (int i = tid; i < GG * B_ROWSB; i += B_THREADS) {
        int r = i & (B_ROWSB - 1), g = i >> 6;
        gls[g * B_ROWSB + r] = g_glT[(size_t)g * BB + b0 + r];
    }
    // stage Wp1 zero-padded to 128 columns
#pragma unroll 4
    for (int i = tid; i < GG * PHP; i += B_THREADS) {
        int g = i >> 7, j = i & (PHP - 1);
        sWp1[i] = (j < PHH) ? Wp1[g * PHH + j] : 0.f;
    }
    if (tid < PHP) {
        sbp1[tid] = (tid < PHH) ? bp1[tid] : 0.f;
        sWp2[tid] = (tid < PHH) ? Wp2[tid] : 0.f;
    }
    __syncthreads();

    const int row  = tid & (B_ROWSB - 1);   // lane -> row (conflict-free LDS)
    const int jsub = tid >> 6;              // warp-uniform j subset
    const int jb   = jsub * 16;

    unsigned long long acc[8];
#pragma unroll
    for (int c = 0; c < 8; c++) acc[c] = 0ull;

#pragma unroll 8
    for (int g = 0; g < GG; g++) {
        float xs = gls[g * B_ROWSB + row];
        unsigned long long xx = f2dup(xs);
        const ulonglong2* wp = (const ulonglong2*)(sWp1 + g * PHP + jb);
        ulonglong2 w0 = wp[0];    // broadcast: j pairs 0..3
        ulonglong2 w1 = wp[1];    // j pairs 4..7
        acc[0] = f2fma(xx, w0.x, acc[0]);
        acc[1] = f2fma(xx, w0.y, acc[1]);
        acc[2] = f2fma(xx, w1.x, acc[2]);
        acc[3] = f2fma(xx, w1.y, acc[3]);
        ulonglong2 w2 = wp[2];
        ulonglong2 w3 = wp[3];
        acc[4] = f2fma(xx, w2.x, acc[4]);
        acc[5] = f2fma(xx, w2.y, acc[5]);
        acc[6] = f2fma(xx, w3.x, acc[6]);
        acc[7] = f2fma(xx, w3.y, acc[7]);
    }

    float o = 0.f;
#pragma unroll
    for (int c = 0; c < 8; c++) {
        int j0 = jb + 2 * c, j1 = j0 + 1;
        float p0 = fmaxf(f2lo(acc[c]) + sbp1[j0], 0.f);
        float p1 = fmaxf(f2hi(acc[c]) + sbp1[j1], 0.f);
        o = fmaf(p0, sWp2[j0], o);
        o = fmaf(p1, sWp2[j1], o);
    }
    op[jsub * B_ROWSB + row] = o;
    __syncthreads();

    if (tid < B_ROWSB) {
        float v = bp2[0];
#pragma unroll
        for (int c = 0; c < 8; c++) v += op[c * B_ROWSB + tid];
        out[b0 + tid] = v;
    }
}

// ---------------------------------------------------------------------------
extern "C" void kernel_launch(void* const* d_in, const int* in_sizes, int n_in,
                              void* d_out, int out_size) {
    const float* x   = (const float*)d_in[0];
    const float* W1  = (const float*)d_in[1];
    const float* b1  = (const float*)d_in[2];
    const float* W2  = (const float*)d_in[3];
    const float* b2  = (const float*)d_in[4];
    const float* Wp1 = (const float*)d_in[5];
    const float* bp1 = (const float*)d_in[6];
    const float* Wp2 = (const float*)d_in[7];
    const float* bp2 = (const float*)d_in[8];
    float* out = (float*)d_out;

    // idempotent, called every launch (no static guards allowed)
    cudaFuncSetAttribute(kernelB, cudaFuncAttributeMaxDynamicSharedMemorySize,
                         B_SMEM_BYTES);

    dim3 gridA(GG, BB / AR);   // concurrent blocks share one contiguous x slab
    kernelA<<<gridA, ATH>>>(x, W1, b1, W2, b2);

    dim3 gridB(BB / B_ROWSB);
    kernelB<<<gridB, B_THREADS, B_SMEM_BYTES>>>(Wp1, bp1, Wp2, bp2, out);
}